// round 16
// baseline (speedup 1.0000x reference)
#include <cuda_runtime.h>
#include <cuda_fp16.h>
#include <cstdint>
#include <math.h>

#define NMAX 100000
#define EMAX 800000
#define HCD  128     // H*C = 4*32
#define NH   4       // heads
#define KVS  384     // per-node halfs in KV: K[128] V[128] Q[128]

// ---------------- scratch ----------------------------------------------------
__device__ __half g_KV[(size_t)NMAX * KVS];
__device__ float  g_Ha[(size_t)NMAX * HCD];       // layer0 out
__device__ float  g_Hb[(size_t)NMAX * HCD];       // layer1 out
__device__ int    g_src[EMAX];
__device__ int    g_dst[EMAX];
__device__ int    g_deg[NMAX + 1];
__device__ int    g_rowptr[NMAX + 1];
__device__ int    g_fill[NMAX];
__device__ int    g_csrc[EMAX];
__device__ float  g_cea[EMAX];
// pre-converted weight fragments (hi/lo fp16 planes, m16n8k16 order)
__device__ uint32_t g_Wf[5][2][8192];   // Wq1,Wk1,Wv1,Ws1,Wc1 (128x128)
__device__ uint32_t g_Wc2f[2][4096];    // Wc2 (128x64)

// ---------------- fp16 HMMA helpers ------------------------------------------
#define A_HI_W 0
#define A_LO_W 8192
#define B_HI_W 16384   // 8192-word B region (32 KB); NC=64 3-term: lo at +4096

__device__ __forceinline__ void mma_f16(float* c, const uint32_t* a, const uint32_t* b) {
    asm volatile(
        "mma.sync.aligned.m16n8k16.row.col.f32.f16.f16.f32 "
        "{%0,%1,%2,%3}, {%4,%5,%6,%7}, {%8,%9}, {%0,%1,%2,%3};"
        : "+f"(c[0]), "+f"(c[1]), "+f"(c[2]), "+f"(c[3])
        : "r"(a[0]), "r"(a[1]), "r"(a[2]), "r"(a[3]), "r"(b[0]), "r"(b[1]));
}

__device__ __forceinline__ uint32_t packh2(__half a, __half b) {
    __half2 h = __halves2half2(a, b);
    return *(uint32_t*)&h;
}

// ---- fill A: 128 rows x 128 k, fp16 hi/lo split, m16n8k16 fragment order -------
template<bool RIN>
__device__ __forceinline__ void fillA(uint32_t* smw, const float* __restrict__ X,
                                      int node0, int n, int tid) {
#pragma unroll
    for (int it = 0; it < 8; it++) {
        int cid = it * 256 + tid;
        int row = cid >> 4;
        int k0  = (cid & 15) << 3;
        int node = node0 + row;
        float4 a = make_float4(0.f, 0.f, 0.f, 0.f), b = a;
        if (node < n) {
            const float4* xp = (const float4*)(X + (size_t)node * 128 + k0);
            a = xp[0]; b = xp[1];
        }
        if (RIN) {
            a.x = fmaxf(a.x, 0.f); a.y = fmaxf(a.y, 0.f);
            a.z = fmaxf(a.z, 0.f); a.w = fmaxf(a.w, 0.f);
            b.x = fmaxf(b.x, 0.f); b.y = fmaxf(b.y, 0.f);
            b.z = fmaxf(b.z, 0.f); b.w = fmaxf(b.w, 0.f);
        }
        float v[8] = {a.x, a.y, a.z, a.w, b.x, b.y, b.z, b.w};
        __half hh[8], hl[8];
#pragma unroll
        for (int j = 0; j < 8; j++) {
            hh[j] = __float2half_rn(v[j]);
            hl[j] = __float2half_rn(v[j] - __half2float(hh[j]));
        }
        int w = row >> 4, r = row & 15;
        int s = k0 >> 4;
        int kk8 = (k0 >> 3) & 1;
        int reg = (r >> 3) + 2 * kk8;
        int lane0 = (r & 7) * 4;
        int base = ((w * 8 + s) * 32 + lane0) * 4 + reg;
#pragma unroll
        for (int p = 0; p < 4; p++) {
            smw[A_HI_W + base + p * 4] = packh2(hh[2 * p], hh[2 * p + 1]);
            smw[A_LO_W + base + p * 4] = packh2(hl[2 * p], hl[2 * p + 1]);
        }
    }
}

// ---- copy a pre-converted fragment plane from global into smem -------------------
template<int WORDS>
__device__ __forceinline__ void copyB(uint32_t* dstw, const uint32_t* __restrict__ gsrc,
                                      int tid) {
#pragma unroll
    for (int it = 0; it < WORDS / 1024; it++) {
        int idx = (it * 256 + tid) * 4;
        uint4 v = __ldg((const uint4*)&gsrc[idx]);
        *(uint4*)&dstw[idx] = v;
    }
}

// ---- split MMA compute (B from smem) ----------------------------------------------
template<int JT, int TERMS>
__device__ __forceinline__ void computeTile(const uint32_t* smw, float acc[][4],
                                            int wid, int lane) {
    constexpr int BLO = B_HI_W + 8 * JT * 64;
#pragma unroll
    for (int s = 0; s < 8; s++) {
        uint4 ah4 = *(const uint4*)&smw[A_HI_W + ((wid * 8 + s) * 32 + lane) * 4];
        uint32_t ah[4] = {ah4.x, ah4.y, ah4.z, ah4.w};
        uint32_t al[4];
        if (TERMS >= 2) {
            uint4 al4 = *(const uint4*)&smw[A_LO_W + ((wid * 8 + s) * 32 + lane) * 4];
            al[0] = al4.x; al[1] = al4.y; al[2] = al4.z; al[3] = al4.w;
        }
#pragma unroll
        for (int j = 0; j < JT; j++) {
            uint2 bh2 = *(const uint2*)&smw[B_HI_W + ((s * JT + j) * 32 + lane) * 2];
            uint32_t bh[2] = {bh2.x, bh2.y};
            mma_f16(acc[j], ah, bh);
            if (TERMS >= 2) mma_f16(acc[j], al, bh);
            if (TERMS == 3) {
                uint2 bl2 = *(const uint2*)&smw[BLO + ((s * JT + j) * 32 + lane) * 2];
                uint32_t bl[2] = {bl2.x, bl2.y};
                mma_f16(acc[j], ah, bl);
            }
        }
    }
}

// ---- store a value pair back into A fragments (for fused classifier) -----------
__device__ __forceinline__ void storeZfrag(uint32_t* smw, int lrow, int col,
                                           float v0, float v1) {
    int w = lrow >> 4, r = lrow & 15;
    int s = col >> 4, kk = col & 15;
    int reg = (r >> 3) + 2 * (kk >> 3);
    int lane = (r & 7) * 4 + ((kk & 7) >> 1);
    int idx = ((w * 8 + s) * 32 + lane) * 4 + reg;
    __half h0 = __float2half_rn(v0), h1 = __float2half_rn(v1);
    smw[A_HI_W + idx] = packh2(h0, h1);
    __half l0 = __float2half_rn(v0 - __half2float(h0));
    __half l1 = __float2half_rn(v1 - __half2float(h1));
    smw[A_LO_W + idx] = packh2(l0, l1);
}

// ---- weight -> fragment conversion (one task = 8 k-values of one out-col) -------
__device__ __forceinline__ void wfrag_task(const float* __restrict__ W, int NC,
                                           uint32_t* __restrict__ hi,
                                           uint32_t* __restrict__ lo, int cid) {
    int nr = cid & (NC - 1);
    int kc = cid / NC;
    int k0 = kc << 3;
    int JT = NC / 8;
    float v[8];
#pragma unroll
    for (int j = 0; j < 8; j++) v[j] = __ldg(&W[(size_t)(k0 + j) * NC + nr]);
    __half hh[8], hl[8];
#pragma unroll
    for (int j = 0; j < 8; j++) {
        hh[j] = __float2half_rn(v[j]);
        hl[j] = __float2half_rn(v[j] - __half2float(hh[j]));
    }
    int j = nr >> 3, nn = nr & 7;
    int s = k0 >> 4;
    int reg = (k0 >> 3) & 1;
    int lane0 = nn * 4;
    int base = ((s * JT + j) * 32 + lane0) * 2 + reg;
#pragma unroll
    for (int p = 0; p < 4; p++) {
        hi[base + p * 2] = packh2(hh[2 * p], hh[2 * p + 1]);
        lo[base + p * 2] = packh2(hl[2 * p], hl[2 * p + 1]);
    }
}

// ---------------- fused: edge_index normalization + weight fragment prep ---------
__global__ void convert_ei_kernel(const int* __restrict__ p, int E, int EB,
                                  int* __restrict__ src, int* __restrict__ dst,
                                  int* __restrict__ deg,
                                  const float* __restrict__ Wq1, const float* __restrict__ Wk1,
                                  const float* __restrict__ Wv1, const float* __restrict__ Ws1,
                                  const float* __restrict__ Wc1, const float* __restrict__ Wc2) {
    if (blockIdx.x < EB) {
        __shared__ int s_is64;
        if (threadIdx.x == 0) {
            int is64 = 1;
            for (int i = 0; i < 64; i++)
                if (p[2 * i + 1] != 0) { is64 = 0; break; }
            s_is64 = is64;
        }
        __syncthreads();
        const int is64 = s_is64;
        int e = blockIdx.x * blockDim.x + threadIdx.x;
        if (e >= E) return;
        int s, d;
        if (is64) { s = p[2 * e]; d = p[2 * (E + e)]; }
        else      { s = p[e];     d = p[E + e]; }
        src[e] = s; dst[e] = d;
        atomicAdd(&deg[d], 1);
    } else {
        int widx = (blockIdx.x - EB) * blockDim.x + threadIdx.x;
        if (widx < 5 * 2048) {
            int mat = widx >> 11;
            int cid = widx & 2047;
            const float* Wlist[5] = {Wq1, Wk1, Wv1, Ws1, Wc1};
            wfrag_task(Wlist[mat], 128, g_Wf[mat][0], g_Wf[mat][1], cid);
        } else if (widx < 5 * 2048 + 1024) {
            wfrag_task(Wc2, 64, g_Wc2f[0], g_Wc2f[1], widx - 5 * 2048);
        }
    }
}

// ---------------- single-block exclusive scan over degrees ----------------------
__global__ void scan_kernel(const int* __restrict__ deg, int* __restrict__ rowptr, int n) {
    __shared__ int sm[1024];
    int tid = threadIdx.x;
    int chunk = (n + 1023) >> 10;
    int start = tid * chunk;
    int end = min(start + chunk, n);
    int sum = 0;
    for (int i = start; i < end; i++) sum += deg[i];
    sm[tid] = sum;
    __syncthreads();
    for (int d = 1; d < 1024; d <<= 1) {
        int v = (tid >= d) ? sm[tid - d] : 0;
        __syncthreads();
        sm[tid] += v;
        __syncthreads();
    }
    int off = sm[tid] - sum;   // exclusive
    for (int i = start; i < end; i++) { rowptr[i] = off; off += deg[i]; }
    if (tid == 1023) rowptr[n] = off;
}

// ---------------- scatter edges into CSR order -----------------------------------
__global__ void scatter_kernel(const int* __restrict__ src, const int* __restrict__ dst,
                               const float* __restrict__ ea,
                               const int* __restrict__ rowptr, int* __restrict__ fill,
                               int* __restrict__ csrc, float* __restrict__ cea, int E) {
    int e = blockIdx.x * blockDim.x + threadIdx.x;
    if (e >= E) return;
    int d = dst[e];
    int pos = rowptr[d] + atomicAdd(&fill[d], 1);
    csrc[pos] = src[e];
    cea[pos]  = ea[e];
}

// ---------------- layer-0 tconv: algebraic collapse (thread per node) ------------
__global__ __launch_bounds__(256)
void tconv0_kernel(const int* __restrict__ rowptr, const int* __restrict__ csrc,
                   const float* __restrict__ cea, const float* __restrict__ x,
                   const float* __restrict__ Wq, const float* __restrict__ bq,
                   const float* __restrict__ Wk, const float* __restrict__ bk,
                   const float* __restrict__ Wv, const float* __restrict__ bv,
                   const float* __restrict__ Ws, const float* __restrict__ bs,
                   const float* __restrict__ We,
                   float* __restrict__ H, int n) {
    __shared__ float sa[256 * 18];
    const int tid = threadIdx.x;
    const int node = blockIdx.x * 256 + tid;
    const float SC = 0.17677669529663687f;   // 1/sqrt(32)

    float A[4], B[4], C[4], QW[4];
    float x0 = 0.f, x1 = 0.f;
    if (node < n) {
        float2 xn = __ldg((const float2*)(x + 2 * (size_t)node));
        x0 = xn.x; x1 = xn.y;
    }
#pragma unroll
    for (int h = 0; h < 4; h++) {
        float a = 0.f, b = 0.f, cc = 0.f, qw = 0.f;
#pragma unroll 8
        for (int j = 0; j < 32; j++) {
            int c = h * 32 + j;
            float qc = fmaf(x0, __ldg(&Wq[c]), fmaf(x1, __ldg(&Wq[HCD + c]), __ldg(&bq[c])));
            a  = fmaf(qc, __ldg(&Wk[c]),       a);
            b  = fmaf(qc, __ldg(&Wk[HCD + c]), b);
            cc = fmaf(qc, __ldg(&bk[c]),       cc);
            qw = fmaf(qc, __ldg(&We[c]),       qw);
        }
        A[h] = a; B[h] = b; C[h] = cc; QW[h] = qw;
    }

    float sx0[4] = {0.f, 0.f, 0.f, 0.f}, sx1[4] = {0.f, 0.f, 0.f, 0.f};
    float den[4] = {0.f, 0.f, 0.f, 0.f}, sev[4] = {0.f, 0.f, 0.f, 0.f};
    int r0 = 0, r1 = 0;
    if (node < n) { r0 = __ldg(&rowptr[node]); r1 = __ldg(&rowptr[node + 1]); }

    int e = r0;
    for (; e + 2 <= r1; e += 2) {
        int   s0 = __ldg(&csrc[e]),  s1 = __ldg(&csrc[e + 1]);
        float a0 = __ldg(&cea[e]),   a1 = __ldg(&cea[e + 1]);
        float2 xa = __ldg((const float2*)(x + 2 * (size_t)s0));
        float2 xb = __ldg((const float2*)(x + 2 * (size_t)s1));
#pragma unroll
        for (int h = 0; h < 4; h++) {
            float p0 = fmaf(xa.x, A[h], fmaf(xa.y, B[h], fmaf(a0, QW[h], C[h])));
            float p1 = fmaf(xb.x, A[h], fmaf(xb.y, B[h], fmaf(a1, QW[h], C[h])));
            float e0 = expf(p0 * SC);
            float e1 = expf(p1 * SC);
            den[h] += e0 + e1;
            sev[h] = fmaf(e0, a0, fmaf(e1, a1, sev[h]));
            sx0[h] = fmaf(e0, xa.x, fmaf(e1, xb.x, sx0[h]));
            sx1[h] = fmaf(e0, xa.y, fmaf(e1, xb.y, sx1[h]));
        }
    }
    if (e < r1) {
        int   s0 = __ldg(&csrc[e]);
        float a0 = __ldg(&cea[e]);
        float2 xa = __ldg((const float2*)(x + 2 * (size_t)s0));
#pragma unroll
        for (int h = 0; h < 4; h++) {
            float p0 = fmaf(xa.x, A[h], fmaf(xa.y, B[h], fmaf(a0, QW[h], C[h])));
            float e0 = expf(p0 * SC);
            den[h] += e0;
            sev[h] = fmaf(e0, a0, sev[h]);
            sx0[h] = fmaf(e0, xa.x, sx0[h]);
            sx1[h] = fmaf(e0, xa.y, sx1[h]);
        }
    }

    float* me = &sa[tid * 18];
#pragma unroll
    for (int h = 0; h < 4; h++) {
        me[h]      = sx0[h];
        me[4 + h]  = sx1[h];
        me[8 + h]  = den[h];
        me[12 + h] = sev[h];
    }
    me[16] = x0; me[17] = x1;
    __syncthreads();

    const int lane = tid & 31, wid = tid >> 5;
    const int c0 = lane * 4;
    const int h  = lane >> 3;
    float4 wv0 = *(const float4*)(Wv + c0);
    float4 wv1 = *(const float4*)(Wv + HCD + c0);
    float4 bv4 = *(const float4*)(bv + c0);
    float4 we4 = *(const float4*)(We + c0);
    float4 ws0 = *(const float4*)(Ws + c0);
    float4 ws1 = *(const float4*)(Ws + HCD + c0);
    float4 bs4 = *(const float4*)(bs + c0);

    for (int i = 0; i < 32; i++) {
        int nl = wid * 32 + i;
        int gnode = blockIdx.x * 256 + nl;
        if (gnode >= n) break;
        const float* acs = &sa[nl * 18];
        float d  = acs[8 + h];
        float s0 = acs[h];
        float s1 = acs[4 + h];
        float sv = acs[12 + h];
        float xa = acs[16], xb = acs[17];
        float inv = 1.f / (d + 1e-16f);
        float4 o;
        o.x = fmaf(xa, ws0.x, fmaf(xb, ws1.x, bs4.x))
            + (wv0.x * s0 + wv1.x * s1 + bv4.x * d + sv * we4.x) * inv;
        o.y = fmaf(xa, ws0.y, fmaf(xb, ws1.y, bs4.y))
            + (wv0.y * s0 + wv1.y * s1 + bv4.y * d + sv * we4.y) * inv;
        o.z = fmaf(xa, ws0.z, fmaf(xb, ws1.z, bs4.z))
            + (wv0.z * s0 + wv1.z * s1 + bv4.z * d + sv * we4.z) * inv;
        o.w = fmaf(xa, ws0.w, fmaf(xb, ws1.w, bs4.w))
            + (wv0.w * s0 + wv1.w * s1 + bv4.w * d + sv * we4.w) * inv;
        *(float4*)(H + (size_t)gnode * HCD + c0) = o;
    }
}

// ---------------- fused 4-projection GEMM (layer 1), fp16 HMMA -------------------
// m=0: Q (fp16 -> KV plane 2). m=1: K. m=2: V. m=3: S (fp32, 3-term).
__global__ __launch_bounds__(256, 2)
void gemm4_hmma(const float* __restrict__ X,
                const float* __restrict__ b0,
                const float* __restrict__ b1,
                const float* __restrict__ b2, __half* __restrict__ KV,
                const float* __restrict__ b3, float* __restrict__ S,
                int n) {
    extern __shared__ uint32_t smw[];
    const int tid = threadIdx.x, wid = tid >> 5, lane = tid & 31;
    const int node0 = blockIdx.x * 128;

    fillA<true>(smw, X, node0, n, tid);

    const float* bm[4] = {b0, b1, b2, b3};
    int row0 = node0 + wid * 16 + (lane >> 2);
    int row1 = row0 + 8;

    for (int m = 0; m < 4; m++) {
        __syncthreads();
        copyB<8192>(&smw[B_HI_W], g_Wf[m][0], tid);   // hi plane
        __syncthreads();

        float acc[16][4];
#pragma unroll
        for (int j = 0; j < 16; j++) {
            float bb0 = __ldg(&bm[m][j * 8 + (lane & 3) * 2]);
            float bb1 = __ldg(&bm[m][j * 8 + (lane & 3) * 2 + 1]);
            acc[j][0] = bb0; acc[j][1] = bb1; acc[j][2] = bb0; acc[j][3] = bb1;
        }
        computeTile<16, 2>(smw, acc, wid, lane);

        if (m == 3) {   // skip path: 3rd term via lo plane second pass
            __syncthreads();
            copyB<8192>(&smw[B_HI_W], g_Wf[m][1], tid);
            __syncthreads();
            computeTile<16, 1>(smw, acc, wid, lane);
#pragma unroll
            for (int j = 0; j < 16; j++) {
                int col = j * 8 + (lane & 3) * 2;
                if (row0 < n) *(float2*)(S + (size_t)row0 * 128 + col) = make_float2(acc[j][0], acc[j][1]);
                if (row1 < n) *(float2*)(S + (size_t)row1 * 128 + col) = make_float2(acc[j][2], acc[j][3]);
            }
        } else {
            int off = (m == 0) ? 256 : ((m == 1) ? 0 : 128);   // Q | K | V planes
#pragma unroll
            for (int j = 0; j < 16; j++) {
                int col = j * 8 + (lane & 3) * 2;
                if (row0 < n) *(__half2*)(KV + (size_t)row0 * KVS + off + col) = __floats2half2_rn(acc[j][0], acc[j][1]);
                if (row1 < n) *(__half2*)(KV + (size_t)row1 * KVS + off + col) = __floats2half2_rn(acc[j][2], acc[j][3]);
            }
        }
    }
}

// ---------------- fused classifier ------------------------------------------------
__global__ __launch_bounds__(256, 2)
void classifier_hmma(const float* __restrict__ X,
                     const float* __restrict__ bc1,
                     const float* __restrict__ bc2,
                     const float* __restrict__ Wc3, const float* __restrict__ bc3,
                     float* __restrict__ out, int n) {
    extern __shared__ uint32_t smw[];
    const int tid = threadIdx.x, wid = tid >> 5, lane = tid & 31;
    const int node0 = blockIdx.x * 128;

    fillA<true>(smw, X, node0, n, tid);
    copyB<8192>(&smw[B_HI_W], g_Wf[4][0], tid);   // Wc1 hi
    __syncthreads();

    float acc[16][4];
#pragma unroll
    for (int j = 0; j < 16; j++) {
        float bb0 = __ldg(&bc1[j * 8 + (lane & 3) * 2]);
        float bb1 = __ldg(&bc1[j * 8 + (lane & 3) * 2 + 1]);
        acc[j][0] = bb0; acc[j][1] = bb1; acc[j][2] = bb0; acc[j][3] = bb1;
    }
    computeTile<16, 2>(smw, acc, wid, lane);
    __syncthreads();
    copyB<8192>(&smw[B_HI_W], g_Wf[4][1], tid);   // Wc1 lo
    __syncthreads();
    computeTile<16, 1>(smw, acc, wid, lane);
    __syncthreads();

    {
        int lr0 = wid * 16 + (lane >> 2);
        int lr1 = lr0 + 8;
#pragma unroll
        for (int j = 0; j < 16; j++) {
            int col = j * 8 + (lane & 3) * 2;
            storeZfrag(smw, lr0, col, fmaxf(acc[j][0], 0.f), fmaxf(acc[j][1], 0.f));
            storeZfrag(smw, lr1, col, fmaxf(acc[j][2], 0.f), fmaxf(acc[j][3], 0.f));
        }
    }
    __syncthreads();
    copyB<4096>(&smw[B_HI_W], g_Wc2f[0], tid);
    copyB<4096>(&smw[B_HI_W + 4096], g_Wc2f[1], tid);
    __syncthreads();

    float acc2[8][4];
#pragma unroll
    for (int j = 0; j < 8; j++) {
        float bb0 = __ldg(&bc2[j * 8 + (lane & 3) * 2]);
        float bb1 = __ldg(&bc2[j * 8 + (lane & 3) * 2 + 1]);
        acc2[j][0] = bb0; acc2[j][1] = bb1; acc2[j][2] = bb0; acc2[j][3] = bb1;
    }
    computeTile<8, 3>(smw, acc2, wid, lane);

    float p0 = 0.f, p1 = 0.f;
#pragma unroll
    for (int j = 0; j < 8; j++) {
        int c = j * 8 + (lane & 3) * 2;
        float w0 = __ldg(&Wc3[c]), w1 = __ldg(&Wc3[c + 1]);
        p0 += fmaxf(acc2[j][0], 0.f) * w0 + fmaxf(acc2[j][1], 0.f) * w1;
        p1 += fmaxf(acc2[j][2], 0.f) * w0 + fmaxf(acc2[j][3], 0.f) * w1;
    }
    p0 += __shfl_xor_sync(0xffffffffu, p0, 1);
    p0 += __shfl_xor_sync(0xffffffffu, p0, 2);
    p1 += __shfl_xor_sync(0xffffffffu, p1, 1);
    p1 += __shfl_xor_sync(0xffffffffu, p1, 2);

    if ((lane & 3) == 0) {
        float bv = __ldg(&bc3[0]);
        int row0 = node0 + wid * 16 + (lane >> 2);
        int row1 = row0 + 8;
        if (row0 < n) out[row0] = p0 + bv;
        if (row1 < n) out[row1] = p1 + bv;
    }
}

// ---------------- layer-1 fused edge kernel (fp16 K/V/Q, unroll 8) ---------------
__global__ __launch_bounds__(256)
void tconv_kernel(const int* __restrict__ rowptr, const int* __restrict__ csrc,
                  const float* __restrict__ cea,
                  const __half* __restrict__ KV, const float* __restrict__ We,
                  float* __restrict__ H, int n) {
    int node = (blockIdx.x * blockDim.x + threadIdx.x) >> 5;
    if (node >= n) return;
    int lane = threadIdx.x & 31;
    int r0 = __ldg(&rowptr[node]);
    int r1 = __ldg(&rowptr[node + 1]);
    int c0 = lane * 4;

    float4 q;
    {
        uint2 qr = *(const uint2*)(KV + (size_t)node * KVS + 256 + c0);
        float2 qa = __half22float2(*(__half2*)&qr.x);
        float2 qb = __half22float2(*(__half2*)&qr.y);
        q = make_float4(qa.x, qa.y, qb.x, qb.y);
    }
    float4 w = *(const float4*)(We + c0);

    float qw = q.x * w.x + q.y * w.y + q.z * w.z + q.w * w.w;
    qw += __shfl_xor_sync(0xffffffffu, qw, 1);
    qw += __shfl_xor_sync(0xffffffffu, qw, 2);
    qw += __shfl_xor_sync(0xffffffffu, qw, 4);

    const float SC = 0.17677669529663687f;
    float den = 0.f, sev = 0.f;
    float4 acc = make_float4(0.f, 0.f, 0.f, 0.f);

    int e = r0;
    for (; e + 8 <= r1; e += 8) {
        int   sN[8];
        float aN[8];
#pragma unroll
        for (int i = 0; i < 8; i++) {
            sN[i] = __ldg(&csrc[e + i]);
            aN[i] = __ldg(&cea[e + i]);
        }
        uint2 kr[8], vr[8];
#pragma unroll
        for (int i = 0; i < 8; i++) {
            const __half* base = KV + (size_t)sN[i] * KVS;
            kr[i] = *(const uint2*)(base + c0);
            vr[i] = *(const uint2*)(base + 128 + c0);
        }
        float p[8];
#pragma unroll
        for (int i = 0; i < 8; i++) {
            float2 kA = __half22float2(*(__half2*)&kr[i].x);
            float2 kB = __half22float2(*(__half2*)&kr[i].y);
            p[i] = q.x * kA.x + q.y * kA.y + q.z * kB.x + q.w * kB.y;
        }
#pragma unroll
        for (int i = 0; i < 8; i++) p[i] += __shfl_xor_sync(0xffffffffu, p[i], 1);
#pragma unroll
        for (int i = 0; i < 8; i++) p[i] += __shfl_xor_sync(0xffffffffu, p[i], 2);
#pragma unroll
        for (int i = 0; i < 8; i++) p[i] += __shfl_xor_sync(0xffffffffu, p[i], 4);
#pragma unroll
        for (int i = 0; i < 8; i++) {
            float ex = expf((p[i] + aN[i] * qw) * SC);
            den += ex;
            sev = fmaf(ex, aN[i], sev);
            float2 vA = __half22float2(*(__half2*)&vr[i].x);
            float2 vB = __half22float2(*(__half2*)&vr[i].y);
            acc.x = fmaf(vA.x, ex, acc.x); acc.y = fmaf(vA.y, ex, acc.y);
            acc.z = fmaf(vB.x, ex, acc.z); acc.w = fmaf(vB.y, ex, acc.w);
        }
    }
    for (; e < r1; e++) {
        int   s0 = __ldg(&csrc[e]);
        float a0 = __ldg(&cea[e]);
        const __half* base = KV + (size_t)s0 * KVS;
        uint2 k0 = *(const uint2*)(base + c0);
        uint2 v0 = *(const uint2*)(base + 128 + c0);
        float2 kA = __half22float2(*(__half2*)&k0.x);
        float2 kB = __half22float2(*(__half2*)&k0.y);
        float p0 = q.x * kA.x + q.y * kA.y + q.z * kB.x + q.w * kB.y;
        p0 += __shfl_xor_sync(0xffffffffu, p0, 1);
        p0 += __shfl_xor_sync(0xffffffffu, p0, 2);
        p0 += __shfl_xor_sync(0xffffffffu, p0, 4);
        float ex0 = expf((p0 + a0 * qw) * SC);
        den += ex0;
        sev += ex0 * a0;
        float2 vA = __half22float2(*(__half2*)&v0.x);
        float2 vB = __half22float2(*(__half2*)&v0.y);
        acc.x = fmaf(vA.x, ex0, acc.x); acc.y = fmaf(vA.y, ex0, acc.y);
        acc.z = fmaf(vB.x, ex0, acc.z); acc.w = fmaf(vB.y, ex0, acc.w);
    }

    float inv = 1.f / (den + 1e-16f);
    float4 out = *(const float4*)(H + (size_t)node * HCD + c0);  // skip term
    out.x = fmaf(fmaf(sev, w.x, acc.x), inv, out.x);
    out.y = fmaf(fmaf(sev, w.y, acc.y), inv, out.y);
    out.z = fmaf(fmaf(sev, w.z, acc.z), inv, out.z);
    out.w = fmaf(fmaf(sev, w.w, acc.w), inv, out.w);
    *(float4*)(H + (size_t)node * HCD + c0) = out;
}

// ---------------- launch -----------------------------------------------------------
extern "C" void kernel_launch(void* const* d_in, const int* in_sizes, int n_in,
                              void* d_out, int out_size) {
    const float* x   = (const float*)d_in[0];
    const int*   eiw = (const int*)d_in[1];
    const float* ea  = (const float*)d_in[2];
    const float *Wq0 = (const float*)d_in[3],  *bq0 = (const float*)d_in[4];
    const float *Wk0 = (const float*)d_in[5],  *bk0 = (const float*)d_in[6];
    const float *Wv0 = (const float*)d_in[7],  *bv0 = (const float*)d_in[8];
    const float *We0 = (const float*)d_in[9];
    const float *Ws0 = (const float*)d_in[10], *bs0 = (const float*)d_in[11];
    const float *Wq1 = (const float*)d_in[12], *bq1 = (const float*)d_in[13];
    const float *Wk1 = (const float*)d_in[14], *bk1 = (const float*)d_in[15];
    const float *Wv1 = (const float*)d_in[16], *bv1 = (const float*)d_in[17];
    const float *We1 = (const float*)d_in[18];
    const float *Ws1 = (const float*)d_in[19], *bs1 = (const float*)d_in[20];
    const float *Wc1 = (const float*)d_in[21], *bc1 = (const float*)d_in[22];
    const float *Wc2 = (const float*)d_in[23], *bc2 = (const float*)d_in[24];
    const float *Wc3 = (const float*)d_in[25], *bc3 = (const float*)d_in[26];

    const int n = in_sizes[0] / 2;
    const int E = in_sizes[2];

    float *Ha, *Hb, *cea;
    __half* KV;
    int *src, *dst, *deg, *rowptr, *fill, *csrc;
    cudaGetSymbolAddress((void**)&KV,     g_KV);
    cudaGetSymbolAddress((void**)&Ha,     g_Ha);
    cudaGetSymbolAddress((void**)&Hb,     g_Hb);
    cudaGetSymbolAddress((void**)&src,    g_src);
    cudaGetSymbolAddress((void**)&dst,    g_dst);
    cudaGetSymbolAddress((void**)&deg,    g_deg);
    cudaGetSymbolAddress((void**)&rowptr, g_rowptr);
    cudaGetSymbolAddress((void**)&fill,   g_fill);
    cudaGetSymbolAddress((void**)&csrc,   g_csrc);
    cudaGetSymbolAddress((void**)&cea,    g_cea);

    const int TB = 256;
    const int EB = (E + TB - 1) / TB;
    const int WB = (5 * 2048 + 1024 + TB - 1) / TB;
    dim3 nodeWarpGrid((n * 32 + TB - 1) / TB);
    dim3 nodeThreadGrid((n + TB - 1) / TB);
    dim3 tileGrid((n + 127) / 128);

    const int SMEM = 24576 * 4;   // 96 KB: A hi/lo (64 KB) + B plane (32 KB)
    cudaFuncSetAttribute(gemm4_hmma,      cudaFuncAttributeMaxDynamicSharedMemorySize, SMEM);
    cudaFuncSetAttribute(classifier_hmma, cudaFuncAttributeMaxDynamicSharedMemorySize, SMEM);

    cudaMemsetAsync(deg,  0, (n + 1) * sizeof(int));
    cudaMemsetAsync(fill, 0, n * sizeof(int));
    convert_ei_kernel<<<EB + WB, TB>>>(eiw, E, EB, src, dst, deg,                   // k1
                                       Wq1, Wk1, Wv1, Ws1, Wc1, Wc2);
    scan_kernel<<<1, 1024>>>(deg, rowptr, n);                                        // k2
    scatter_kernel<<<EB, TB>>>(src, dst, ea, rowptr, fill, csrc, cea, E);            // k3
    tconv0_kernel<<<nodeThreadGrid, TB>>>(rowptr, csrc, cea, x,                      // k4 <- profiled
                                          Wq0, bq0, Wk0, bk0, Wv0, bv0, Ws0, bs0,
                                          We0, Ha, n);
    gemm4_hmma<<<tileGrid, 256, SMEM>>>(Ha, bq1, bk1, bv1, KV, bs1, Hb, n);          // k5
    tconv_kernel<<<nodeWarpGrid, TB>>>(rowptr, csrc, cea, KV, We1, Hb, n);           // k6
    classifier_hmma<<<tileGrid, 256, SMEM>>>(Hb, bc1, bc2, Wc3, bc3,                 // k7
                                             (float*)d_out, n);
}

// round 17
// speedup vs baseline: 1.1020x; 1.1020x over previous
#include <cuda_runtime.h>
#include <cuda_fp16.h>
#include <cstdint>
#include <math.h>

#define NMAX 100000
#define EMAX 800000
#define HCD  128     // H*C = 4*32
#define NH   4       // heads

// ---------------- scratch ----------------------------------------------------
__device__ float  g_Q [(size_t)NMAX * HCD];       // Q (layer 1)
__device__ __half g_KV[(size_t)NMAX * 2 * HCD];   // per node: 128 K halfs, 128 V halfs
__device__ float  g_Ha[(size_t)NMAX * HCD];       // layer0 out
__device__ float  g_Hb[(size_t)NMAX * HCD];       // layer1 out
__device__ int    g_src[EMAX];
__device__ int    g_dst[EMAX];
__device__ int    g_deg[NMAX + 1];
__device__ int    g_rowptr[NMAX + 1];
__device__ int    g_fill[NMAX];
__device__ int    g_csrc[EMAX];
__device__ float  g_cea[EMAX];
// pre-converted weight fragments (hi/lo fp16 planes, m16n8k16 order)
__device__ uint32_t g_Wf[5][2][8192];   // Wq1,Wk1,Wv1,Ws1,Wc1 (128x128)
__device__ uint32_t g_Wc2f[2][4096];    // Wc2 (128x64)

// ---------------- fp16 HMMA helpers ------------------------------------------
#define A_HI_W 0
#define A_LO_W 8192
#define B_HI_W 16384   // 8192-word B region (32 KB); NC=64 3-term: lo at +4096

__device__ __forceinline__ void mma_f16(float* c, const uint32_t* a, const uint32_t* b) {
    asm volatile(
        "mma.sync.aligned.m16n8k16.row.col.f32.f16.f16.f32 "
        "{%0,%1,%2,%3}, {%4,%5,%6,%7}, {%8,%9}, {%0,%1,%2,%3};"
        : "+f"(c[0]), "+f"(c[1]), "+f"(c[2]), "+f"(c[3])
        : "r"(a[0]), "r"(a[1]), "r"(a[2]), "r"(a[3]), "r"(b[0]), "r"(b[1]));
}

__device__ __forceinline__ uint32_t packh2(__half a, __half b) {
    __half2 h = __halves2half2(a, b);
    return *(uint32_t*)&h;
}

// ---- fill A: 128 rows x 128 k, fp16 hi/lo split, m16n8k16 fragment order -------
template<bool RIN>
__device__ __forceinline__ void fillA(uint32_t* smw, const float* __restrict__ X,
                                      int node0, int n, int tid) {
#pragma unroll
    for (int it = 0; it < 8; it++) {
        int cid = it * 256 + tid;
        int row = cid >> 4;
        int k0  = (cid & 15) << 3;
        int node = node0 + row;
        float4 a = make_float4(0.f, 0.f, 0.f, 0.f), b = a;
        if (node < n) {
            const float4* xp = (const float4*)(X + (size_t)node * 128 + k0);
            a = xp[0]; b = xp[1];
        }
        if (RIN) {
            a.x = fmaxf(a.x, 0.f); a.y = fmaxf(a.y, 0.f);
            a.z = fmaxf(a.z, 0.f); a.w = fmaxf(a.w, 0.f);
            b.x = fmaxf(b.x, 0.f); b.y = fmaxf(b.y, 0.f);
            b.z = fmaxf(b.z, 0.f); b.w = fmaxf(b.w, 0.f);
        }
        float v[8] = {a.x, a.y, a.z, a.w, b.x, b.y, b.z, b.w};
        __half hh[8], hl[8];
#pragma unroll
        for (int j = 0; j < 8; j++) {
            hh[j] = __float2half_rn(v[j]);
            hl[j] = __float2half_rn(v[j] - __half2float(hh[j]));
        }
        int w = row >> 4, r = row & 15;
        int s = k0 >> 4;
        int kk8 = (k0 >> 3) & 1;
        int reg = (r >> 3) + 2 * kk8;
        int lane0 = (r & 7) * 4;
        int base = ((w * 8 + s) * 32 + lane0) * 4 + reg;
#pragma unroll
        for (int p = 0; p < 4; p++) {
            smw[A_HI_W + base + p * 4] = packh2(hh[2 * p], hh[2 * p + 1]);
            smw[A_LO_W + base + p * 4] = packh2(hl[2 * p], hl[2 * p + 1]);
        }
    }
}

// ---- copy a pre-converted fragment plane from global into smem -------------------
template<int WORDS>
__device__ __forceinline__ void copyB(uint32_t* dstw, const uint32_t* __restrict__ gsrc,
                                      int tid) {
#pragma unroll
    for (int it = 0; it < WORDS / 1024; it++) {
        int idx = (it * 256 + tid) * 4;
        uint4 v = __ldg((const uint4*)&gsrc[idx]);
        *(uint4*)&dstw[idx] = v;
    }
}

// ---- split MMA compute (B from smem) ----------------------------------------------
template<int JT, int TERMS>
__device__ __forceinline__ void computeTile(const uint32_t* smw, float acc[][4],
                                            int wid, int lane) {
    constexpr int BLO = B_HI_W + 8 * JT * 64;
#pragma unroll
    for (int s = 0; s < 8; s++) {
        uint4 ah4 = *(const uint4*)&smw[A_HI_W + ((wid * 8 + s) * 32 + lane) * 4];
        uint32_t ah[4] = {ah4.x, ah4.y, ah4.z, ah4.w};
        uint32_t al[4];
        if (TERMS >= 2) {
            uint4 al4 = *(const uint4*)&smw[A_LO_W + ((wid * 8 + s) * 32 + lane) * 4];
            al[0] = al4.x; al[1] = al4.y; al[2] = al4.z; al[3] = al4.w;
        }
#pragma unroll
        for (int j = 0; j < JT; j++) {
            uint2 bh2 = *(const uint2*)&smw[B_HI_W + ((s * JT + j) * 32 + lane) * 2];
            uint32_t bh[2] = {bh2.x, bh2.y};
            mma_f16(acc[j], ah, bh);
            if (TERMS >= 2) mma_f16(acc[j], al, bh);
            if (TERMS == 3) {
                uint2 bl2 = *(const uint2*)&smw[BLO + ((s * JT + j) * 32 + lane) * 2];
                uint32_t bl[2] = {bl2.x, bl2.y};
                mma_f16(acc[j], ah, bl);
            }
        }
    }
}

// ---- store a value pair back into A fragments (for fused classifier) -----------
__device__ __forceinline__ void storeZfrag(uint32_t* smw, int lrow, int col,
                                           float v0, float v1) {
    int w = lrow >> 4, r = lrow & 15;
    int s = col >> 4, kk = col & 15;
    int reg = (r >> 3) + 2 * (kk >> 3);
    int lane = (r & 7) * 4 + ((kk & 7) >> 1);
    int idx = ((w * 8 + s) * 32 + lane) * 4 + reg;
    __half h0 = __float2half_rn(v0), h1 = __float2half_rn(v1);
    smw[A_HI_W + idx] = packh2(h0, h1);
    __half l0 = __float2half_rn(v0 - __half2float(h0));
    __half l1 = __float2half_rn(v1 - __half2float(h1));
    smw[A_LO_W + idx] = packh2(l0, l1);
}

// ---- weight -> fragment conversion (one task = 8 k-values of one out-col) -------
__device__ __forceinline__ void wfrag_task(const float* __restrict__ W, int NC,
                                           uint32_t* __restrict__ hi,
                                           uint32_t* __restrict__ lo, int cid) {
    int nr = cid & (NC - 1);
    int kc = cid / NC;
    int k0 = kc << 3;
    int JT = NC / 8;
    float v[8];
#pragma unroll
    for (int j = 0; j < 8; j++) v[j] = __ldg(&W[(size_t)(k0 + j) * NC + nr]);
    __half hh[8], hl[8];
#pragma unroll
    for (int j = 0; j < 8; j++) {
        hh[j] = __float2half_rn(v[j]);
        hl[j] = __float2half_rn(v[j] - __half2float(hh[j]));
    }
    int j = nr >> 3, nn = nr & 7;
    int s = k0 >> 4;
    int reg = (k0 >> 3) & 1;
    int lane0 = nn * 4;
    int base = ((s * JT + j) * 32 + lane0) * 2 + reg;
#pragma unroll
    for (int p = 0; p < 4; p++) {
        hi[base + p * 2] = packh2(hh[2 * p], hh[2 * p + 1]);
        lo[base + p * 2] = packh2(hl[2 * p], hl[2 * p + 1]);
    }
}

// ---------------- fused: edge_index normalization + weight fragment prep ---------
__global__ void convert_ei_kernel(const int* __restrict__ p, int E, int EB,
                                  int* __restrict__ src, int* __restrict__ dst,
                                  int* __restrict__ deg,
                                  const float* __restrict__ Wq1, const float* __restrict__ Wk1,
                                  const float* __restrict__ Wv1, const float* __restrict__ Ws1,
                                  const float* __restrict__ Wc1, const float* __restrict__ Wc2) {
    if (blockIdx.x < EB) {
        __shared__ int s_is64;
        if (threadIdx.x == 0) {
            int is64 = 1;
            for (int i = 0; i < 64; i++)
                if (p[2 * i + 1] != 0) { is64 = 0; break; }
            s_is64 = is64;
        }
        __syncthreads();
        const int is64 = s_is64;
        int e = blockIdx.x * blockDim.x + threadIdx.x;
        if (e >= E) return;
        int s, d;
        if (is64) { s = p[2 * e]; d = p[2 * (E + e)]; }
        else      { s = p[e];     d = p[E + e]; }
        src[e] = s; dst[e] = d;
        atomicAdd(&deg[d], 1);
    } else {
        int widx = (blockIdx.x - EB) * blockDim.x + threadIdx.x;
        if (widx < 5 * 2048) {
            int mat = widx >> 11;
            int cid = widx & 2047;
            const float* Wlist[5] = {Wq1, Wk1, Wv1, Ws1, Wc1};
            wfrag_task(Wlist[mat], 128, g_Wf[mat][0], g_Wf[mat][1], cid);
        } else if (widx < 5 * 2048 + 1024) {
            wfrag_task(Wc2, 64, g_Wc2f[0], g_Wc2f[1], widx - 5 * 2048);
        }
    }
}

// ---------------- single-block exclusive scan over degrees ----------------------
__global__ void scan_kernel(const int* __restrict__ deg, int* __restrict__ rowptr, int n) {
    __shared__ int sm[1024];
    int tid = threadIdx.x;
    int chunk = (n + 1023) >> 10;
    int start = tid * chunk;
    int end = min(start + chunk, n);
    int sum = 0;
    for (int i = start; i < end; i++) sum += deg[i];
    sm[tid] = sum;
    __syncthreads();
    for (int d = 1; d < 1024; d <<= 1) {
        int v = (tid >= d) ? sm[tid - d] : 0;
        __syncthreads();
        sm[tid] += v;
        __syncthreads();
    }
    int off = sm[tid] - sum;   // exclusive
    for (int i = start; i < end; i++) { rowptr[i] = off; off += deg[i]; }
    if (tid == 1023) rowptr[n] = off;
}

// ---------------- scatter edges into CSR order -----------------------------------
__global__ void scatter_kernel(const int* __restrict__ src, const int* __restrict__ dst,
                               const float* __restrict__ ea,
                               const int* __restrict__ rowptr, int* __restrict__ fill,
                               int* __restrict__ csrc, float* __restrict__ cea, int E) {
    int e = blockIdx.x * blockDim.x + threadIdx.x;
    if (e >= E) return;
    int d = dst[e];
    int pos = rowptr[d] + atomicAdd(&fill[d], 1);
    csrc[pos] = src[e];
    cea[pos]  = ea[e];
}

// ---------------- layer-0 tconv: algebraic collapse (thread per node) ------------
__global__ __launch_bounds__(256)
void tconv0_kernel(const int* __restrict__ rowptr, const int* __restrict__ csrc,
                   const float* __restrict__ cea, const float* __restrict__ x,
                   const float* __restrict__ Wq, const float* __restrict__ bq,
                   const float* __restrict__ Wk, const float* __restrict__ bk,
                   const float* __restrict__ Wv, const float* __restrict__ bv,
                   const float* __restrict__ Ws, const float* __restrict__ bs,
                   const float* __restrict__ We,
                   float* __restrict__ H, int n) {
    __shared__ float sa[256 * 18];
    const int tid = threadIdx.x;
    const int node = blockIdx.x * 256 + tid;
    const float SC = 0.17677669529663687f;   // 1/sqrt(32)

    float A[4], B[4], C[4], QW[4];
    float x0 = 0.f, x1 = 0.f;
    if (node < n) {
        float2 xn = __ldg((const float2*)(x + 2 * (size_t)node));
        x0 = xn.x; x1 = xn.y;
    }
#pragma unroll
    for (int h = 0; h < 4; h++) {
        float a = 0.f, b = 0.f, cc = 0.f, qw = 0.f;
#pragma unroll 8
        for (int j = 0; j < 32; j++) {
            int c = h * 32 + j;
            float qc = fmaf(x0, __ldg(&Wq[c]), fmaf(x1, __ldg(&Wq[HCD + c]), __ldg(&bq[c])));
            a  = fmaf(qc, __ldg(&Wk[c]),       a);
            b  = fmaf(qc, __ldg(&Wk[HCD + c]), b);
            cc = fmaf(qc, __ldg(&bk[c]),       cc);
            qw = fmaf(qc, __ldg(&We[c]),       qw);
        }
        A[h] = a; B[h] = b; C[h] = cc; QW[h] = qw;
    }

    float sx0[4] = {0.f, 0.f, 0.f, 0.f}, sx1[4] = {0.f, 0.f, 0.f, 0.f};
    float den[4] = {0.f, 0.f, 0.f, 0.f}, sev[4] = {0.f, 0.f, 0.f, 0.f};
    int r0 = 0, r1 = 0;
    if (node < n) { r0 = __ldg(&rowptr[node]); r1 = __ldg(&rowptr[node + 1]); }

    int e = r0;
    for (; e + 2 <= r1; e += 2) {
        int   s0 = __ldg(&csrc[e]),  s1 = __ldg(&csrc[e + 1]);
        float a0 = __ldg(&cea[e]),   a1 = __ldg(&cea[e + 1]);
        float2 xa = __ldg((const float2*)(x + 2 * (size_t)s0));
        float2 xb = __ldg((const float2*)(x + 2 * (size_t)s1));
#pragma unroll
        for (int h = 0; h < 4; h++) {
            float p0 = fmaf(xa.x, A[h], fmaf(xa.y, B[h], fmaf(a0, QW[h], C[h])));
            float p1 = fmaf(xb.x, A[h], fmaf(xb.y, B[h], fmaf(a1, QW[h], C[h])));
            float e0 = expf(p0 * SC);
            float e1 = expf(p1 * SC);
            den[h] += e0 + e1;
            sev[h] = fmaf(e0, a0, fmaf(e1, a1, sev[h]));
            sx0[h] = fmaf(e0, xa.x, fmaf(e1, xb.x, sx0[h]));
            sx1[h] = fmaf(e0, xa.y, fmaf(e1, xb.y, sx1[h]));
        }
    }
    if (e < r1) {
        int   s0 = __ldg(&csrc[e]);
        float a0 = __ldg(&cea[e]);
        float2 xa = __ldg((const float2*)(x + 2 * (size_t)s0));
#pragma unroll
        for (int h = 0; h < 4; h++) {
            float p0 = fmaf(xa.x, A[h], fmaf(xa.y, B[h], fmaf(a0, QW[h], C[h])));
            float e0 = expf(p0 * SC);
            den[h] += e0;
            sev[h] = fmaf(e0, a0, sev[h]);
            sx0[h] = fmaf(e0, xa.x, sx0[h]);
            sx1[h] = fmaf(e0, xa.y, sx1[h]);
        }
    }

    float* me = &sa[tid * 18];
#pragma unroll
    for (int h = 0; h < 4; h++) {
        me[h]      = sx0[h];
        me[4 + h]  = sx1[h];
        me[8 + h]  = den[h];
        me[12 + h] = sev[h];
    }
    me[16] = x0; me[17] = x1;
    __syncthreads();

    const int lane = tid & 31, wid = tid >> 5;
    const int c0 = lane * 4;
    const int h  = lane >> 3;
    float4 wv0 = *(const float4*)(Wv + c0);
    float4 wv1 = *(const float4*)(Wv + HCD + c0);
    float4 bv4 = *(const float4*)(bv + c0);
    float4 we4 = *(const float4*)(We + c0);
    float4 ws0 = *(const float4*)(Ws + c0);
    float4 ws1 = *(const float4*)(Ws + HCD + c0);
    float4 bs4 = *(const float4*)(bs + c0);

    for (int i = 0; i < 32; i++) {
        int nl = wid * 32 + i;
        int gnode = blockIdx.x * 256 + nl;
        if (gnode >= n) break;
        const float* acs = &sa[nl * 18];
        float d  = acs[8 + h];
        float s0 = acs[h];
        float s1 = acs[4 + h];
        float sv = acs[12 + h];
        float xa = acs[16], xb = acs[17];
        float inv = 1.f / (d + 1e-16f);
        float4 o;
        o.x = fmaf(xa, ws0.x, fmaf(xb, ws1.x, bs4.x))
            + (wv0.x * s0 + wv1.x * s1 + bv4.x * d + sv * we4.x) * inv;
        o.y = fmaf(xa, ws0.y, fmaf(xb, ws1.y, bs4.y))
            + (wv0.y * s0 + wv1.y * s1 + bv4.y * d + sv * we4.y) * inv;
        o.z = fmaf(xa, ws0.z, fmaf(xb, ws1.z, bs4.z))
            + (wv0.z * s0 + wv1.z * s1 + bv4.z * d + sv * we4.z) * inv;
        o.w = fmaf(xa, ws0.w, fmaf(xb, ws1.w, bs4.w))
            + (wv0.w * s0 + wv1.w * s1 + bv4.w * d + sv * we4.w) * inv;
        *(float4*)(H + (size_t)gnode * HCD + c0) = o;
    }
}

// ---------------- fused 4-projection GEMM (layer 1), fp16 HMMA -------------------
// All four matrices: 2-term split (Ahi+Alo) x Bhi.
__global__ __launch_bounds__(256, 2)
void gemm4_hmma(const float* __restrict__ X,
                const float* __restrict__ b0, float* __restrict__ Q,
                const float* __restrict__ b1,
                const float* __restrict__ b2, __half* __restrict__ KV,
                const float* __restrict__ b3, float* __restrict__ S,
                int n) {
    extern __shared__ uint32_t smw[];
    const int tid = threadIdx.x, wid = tid >> 5, lane = tid & 31;
    const int node0 = blockIdx.x * 128;

    fillA<true>(smw, X, node0, n, tid);

    const float* bm[4] = {b0, b1, b2, b3};
    int row0 = node0 + wid * 16 + (lane >> 2);
    int row1 = row0 + 8;

    for (int m = 0; m < 4; m++) {
        __syncthreads();
        copyB<8192>(&smw[B_HI_W], g_Wf[m][0], tid);   // hi plane
        __syncthreads();

        float acc[16][4];
#pragma unroll
        for (int j = 0; j < 16; j++) {
            float bb0 = __ldg(&bm[m][j * 8 + (lane & 3) * 2]);
            float bb1 = __ldg(&bm[m][j * 8 + (lane & 3) * 2 + 1]);
            acc[j][0] = bb0; acc[j][1] = bb1; acc[j][2] = bb0; acc[j][3] = bb1;
        }
        computeTile<16, 2>(smw, acc, wid, lane);

        if (m == 0 || m == 3) {
            float* Y = (m == 0) ? Q : S;
#pragma unroll
            for (int j = 0; j < 16; j++) {
                int col = j * 8 + (lane & 3) * 2;
                if (row0 < n) *(float2*)(Y + (size_t)row0 * 128 + col) = make_float2(acc[j][0], acc[j][1]);
                if (row1 < n) *(float2*)(Y + (size_t)row1 * 128 + col) = make_float2(acc[j][2], acc[j][3]);
            }
        } else {
            int off = (m == 1) ? 0 : 128;
#pragma unroll
            for (int j = 0; j < 16; j++) {
                int col = j * 8 + (lane & 3) * 2;
                if (row0 < n) *(__half2*)(KV + (size_t)row0 * 256 + off + col) = __floats2half2_rn(acc[j][0], acc[j][1]);
                if (row1 < n) *(__half2*)(KV + (size_t)row1 * 256 + off + col) = __floats2half2_rn(acc[j][2], acc[j][3]);
            }
        }
    }
}

// ---------------- fused classifier ------------------------------------------------
// Wc1: 2-term.  Wc2: 3-term single-pass.  Final dot fp32.
__global__ __launch_bounds__(256, 2)
void classifier_hmma(const float* __restrict__ X,
                     const float* __restrict__ bc1,
                     const float* __restrict__ bc2,
                     const float* __restrict__ Wc3, const float* __restrict__ bc3,
                     float* __restrict__ out, int n) {
    extern __shared__ uint32_t smw[];
    const int tid = threadIdx.x, wid = tid >> 5, lane = tid & 31;
    const int node0 = blockIdx.x * 128;

    fillA<true>(smw, X, node0, n, tid);
    copyB<8192>(&smw[B_HI_W], g_Wf[4][0], tid);   // Wc1 hi
    __syncthreads();

    // stage 1: Z1 = relu(X @ Wc1 + bc1), 2-term
    float acc[16][4];
#pragma unroll
    for (int j = 0; j < 16; j++) {
        float bb0 = __ldg(&bc1[j * 8 + (lane & 3) * 2]);
        float bb1 = __ldg(&bc1[j * 8 + (lane & 3) * 2 + 1]);
        acc[j][0] = bb0; acc[j][1] = bb1; acc[j][2] = bb0; acc[j][3] = bb1;
    }
    computeTile<16, 2>(smw, acc, wid, lane);
    __syncthreads();   // all warps done reading A

    {
        int lr0 = wid * 16 + (lane >> 2);
        int lr1 = lr0 + 8;
#pragma unroll
        for (int j = 0; j < 16; j++) {
            int col = j * 8 + (lane & 3) * 2;
            storeZfrag(smw, lr0, col, fmaxf(acc[j][0], 0.f), fmaxf(acc[j][1], 0.f));
            storeZfrag(smw, lr1, col, fmaxf(acc[j][2], 0.f), fmaxf(acc[j][3], 0.f));
        }
    }
    __syncthreads();
    copyB<4096>(&smw[B_HI_W], g_Wc2f[0], tid);
    copyB<4096>(&smw[B_HI_W + 4096], g_Wc2f[1], tid);
    __syncthreads();

    // stage 2: Z2 = relu(Z1 @ Wc2 + bc2), 64 cols, single-pass 3-term
    float acc2[8][4];
#pragma unroll
    for (int j = 0; j < 8; j++) {
        float bb0 = __ldg(&bc2[j * 8 + (lane & 3) * 2]);
        float bb1 = __ldg(&bc2[j * 8 + (lane & 3) * 2 + 1]);
        acc2[j][0] = bb0; acc2[j][1] = bb1; acc2[j][2] = bb0; acc2[j][3] = bb1;
    }
    computeTile<8, 3>(smw, acc2, wid, lane);

    // stage 3: out = relu(Z2) @ Wc3 + bc3
    float p0 = 0.f, p1 = 0.f;
#pragma unroll
    for (int j = 0; j < 8; j++) {
        int c = j * 8 + (lane & 3) * 2;
        float w0 = __ldg(&Wc3[c]), w1 = __ldg(&Wc3[c + 1]);
        p0 += fmaxf(acc2[j][0], 0.f) * w0 + fmaxf(acc2[j][1], 0.f) * w1;
        p1 += fmaxf(acc2[j][2], 0.f) * w0 + fmaxf(acc2[j][3], 0.f) * w1;
    }
    p0 += __shfl_xor_sync(0xffffffffu, p0, 1);
    p0 += __shfl_xor_sync(0xffffffffu, p0, 2);
    p1 += __shfl_xor_sync(0xffffffffu, p1, 1);
    p1 += __shfl_xor_sync(0xffffffffu, p1, 2);

    if ((lane & 3) == 0) {
        float bv = __ldg(&bc3[0]);
        int row0 = node0 + wid * 16 + (lane >> 2);
        int row1 = row0 + 8;
        if (row0 < n) out[row0] = p0 + bv;
        if (row1 < n) out[row1] = p1 + bv;
    }
}

// ---------------- layer-1 fused edge kernel (fp16 KV gather, unroll 4) -----------
__global__ __launch_bounds__(256)
void tconv_kernel(const int* __restrict__ rowptr, const int* __restrict__ csrc,
                  const float* __restrict__ cea,
                  const float* __restrict__ Q, const __half* __restrict__ KV,
                  const float* __restrict__ We,
                  float* __restrict__ H, int n) {
    int node = (blockIdx.x * blockDim.x + threadIdx.x) >> 5;
    if (node >= n) return;
    int lane = threadIdx.x & 31;
    int r0 = __ldg(&rowptr[node]);
    int r1 = __ldg(&rowptr[node + 1]);
    int c0 = lane * 4;

    float4 q = *(const float4*)(Q + (size_t)node * HCD + c0);
    float4 w = *(const float4*)(We + c0);

    float qw = q.x * w.x + q.y * w.y + q.z * w.z + q.w * w.w;
    qw += __shfl_xor_sync(0xffffffffu, qw, 1);
    qw += __shfl_xor_sync(0xffffffffu, qw, 2);
    qw += __shfl_xor_sync(0xffffffffu, qw, 4);

    const float SC = 0.17677669529663687f;
    float den = 0.f, sev = 0.f;
    float4 acc = make_float4(0.f, 0.f, 0.f, 0.f);

    int e = r0;
    for (; e + 4 <= r1; e += 4) {
        int   s0 = __ldg(&csrc[e]),     s1 = __ldg(&csrc[e + 1]);
        int   s2 = __ldg(&csrc[e + 2]), s3 = __ldg(&csrc[e + 3]);
        float a0 = __ldg(&cea[e]),      a1 = __ldg(&cea[e + 1]);
        float a2 = __ldg(&cea[e + 2]),  a3 = __ldg(&cea[e + 3]);

        uint2 k0 = *(const uint2*)(KV + (size_t)s0 * 256 + c0);
        uint2 k1 = *(const uint2*)(KV + (size_t)s1 * 256 + c0);
        uint2 k2 = *(const uint2*)(KV + (size_t)s2 * 256 + c0);
        uint2 k3 = *(const uint2*)(KV + (size_t)s3 * 256 + c0);
        uint2 v0 = *(const uint2*)(KV + (size_t)s0 * 256 + 128 + c0);
        uint2 v1 = *(const uint2*)(KV + (size_t)s1 * 256 + 128 + c0);
        uint2 v2 = *(const uint2*)(KV + (size_t)s2 * 256 + 128 + c0);
        uint2 v3 = *(const uint2*)(KV + (size_t)s3 * 256 + 128 + c0);

        float2 kA, kB;
        kA = __half22float2(*(__half2*)&k0.x); kB = __half22float2(*(__half2*)&k0.y);
        float p0 = q.x * kA.x + q.y * kA.y + q.z * kB.x + q.w * kB.y;
        kA = __half22float2(*(__half2*)&k1.x); kB = __half22float2(*(__half2*)&k1.y);
        float p1 = q.x * kA.x + q.y * kA.y + q.z * kB.x + q.w * kB.y;
        kA = __half22float2(*(__half2*)&k2.x); kB = __half22float2(*(__half2*)&k2.y);
        float p2 = q.x * kA.x + q.y * kA.y + q.z * kB.x + q.w * kB.y;
        kA = __half22float2(*(__half2*)&k3.x); kB = __half22float2(*(__half2*)&k3.y);
        float p3 = q.x * kA.x + q.y * kA.y + q.z * kB.x + q.w * kB.y;

        p0 += __shfl_xor_sync(0xffffffffu, p0, 1);
        p1 += __shfl_xor_sync(0xffffffffu, p1, 1);
        p2 += __shfl_xor_sync(0xffffffffu, p2, 1);
        p3 += __shfl_xor_sync(0xffffffffu, p3, 1);
        p0 += __shfl_xor_sync(0xffffffffu, p0, 2);
        p1 += __shfl_xor_sync(0xffffffffu, p1, 2);
        p2 += __shfl_xor_sync(0xffffffffu, p2, 2);
        p3 += __shfl_xor_sync(0xffffffffu, p3, 2);
        p0 += __shfl_xor_sync(0xffffffffu, p0, 4);
        p1 += __shfl_xor_sync(0xffffffffu, p1, 4);
        p2 += __shfl_xor_sync(0xffffffffu, p2, 4);
        p3 += __shfl_xor_sync(0xffffffffu, p3, 4);

        float ex0 = expf((p0 + a0 * qw) * SC);
        float ex1 = expf((p1 + a1 * qw) * SC);
        float ex2 = expf((p2 + a2 * qw) * SC);
        float ex3 = expf((p3 + a3 * qw) * SC);

        den += (ex0 + ex1) + (ex2 + ex3);
        sev += (ex0 * a0 + ex1 * a1) + (ex2 * a2 + ex3 * a3);

        float2 vA, vB;
        vA = __half22float2(*(__half2*)&v0.x); vB = __half22float2(*(__half2*)&v0.y);
        acc.x = fmaf(vA.x, ex0, acc.x); acc.y = fmaf(vA.y, ex0, acc.y);
        acc.z = fmaf(vB.x, ex0, acc.z); acc.w = fmaf(vB.y, ex0, acc.w);
        vA = __half22float2(*(__half2*)&v1.x); vB = __half22float2(*(__half2*)&v1.y);
        acc.x = fmaf(vA.x, ex1, acc.x); acc.y = fmaf(vA.y, ex1, acc.y);
        acc.z = fmaf(vB.x, ex1, acc.z); acc.w = fmaf(vB.y, ex1, acc.w);
        vA = __half22float2(*(__half2*)&v2.x); vB = __half22float2(*(__half2*)&v2.y);
        acc.x = fmaf(vA.x, ex2, acc.x); acc.y = fmaf(vA.y, ex2, acc.y);
        acc.z = fmaf(vB.x, ex2, acc.z); acc.w = fmaf(vB.y, ex2, acc.w);
        vA = __half22float2(*(__half2*)&v3.x); vB = __half22float2(*(__half2*)&v3.y);
        acc.x = fmaf(vA.x, ex3, acc.x); acc.y = fmaf(vA.y, ex3, acc.y);
        acc.z = fmaf(vB.x, ex3, acc.z); acc.w = fmaf(vB.y, ex3, acc.w);
    }
    for (; e < r1; e++) {
        int   s0 = __ldg(&csrc[e]);
        float a0 = __ldg(&cea[e]);
        uint2 k0 = *(const uint2*)(KV + (size_t)s0 * 256 + c0);
        uint2 v0 = *(const uint2*)(KV + (size_t)s0 * 256 + 128 + c0);
        float2 kA = __half22float2(*(__half2*)&k0.x);
        float2 kB = __half22float2(*(__half2*)&k0.y);
        float p0 = q.x * kA.x + q.y * kA.y + q.z * kB.x + q.w * kB.y;
        p0 += __shfl_xor_sync(0xffffffffu, p0, 1);
        p0 += __shfl_xor_sync(0xffffffffu, p0, 2);
        p0 += __shfl_xor_sync(0xffffffffu, p0, 4);
        float ex0 = expf((p0 + a0 * qw) * SC);
        den += ex0;
        sev += ex0 * a0;
        float2 vA = __half22float2(*(__half2*)&v0.x);
        float2 vB = __half22float2(*(__half2*)&v0.y);
        acc.x = fmaf(vA.x, ex0, acc.x); acc.y = fmaf(vA.y, ex0, acc.y);
        acc.z = fmaf(vB.x, ex0, acc.z); acc.w = fmaf(vB.y, ex0, acc.w);
    }

    float inv = 1.f / (den + 1e-16f);
    float4 out = *(const float4*)(H + (size_t)node * HCD + c0);  // skip term
    out.x = fmaf(fmaf(sev, w.x, acc.x), inv, out.x);
    out.y = fmaf(fmaf(sev, w.y, acc.y), inv, out.y);
    out.z = fmaf(fmaf(sev, w.z, acc.z), inv, out.z);
    out.w = fmaf(fmaf(sev, w.w, acc.w), inv, out.w);
    *(float4*)(H + (size_t)node * HCD + c0) = out;
}

// ---------------- launch -----------------------------------------------------------
extern "C" void kernel_launch(void* const* d_in, const int* in_sizes, int n_in,
                              void* d_out, int out_size) {
    const float* x   = (const float*)d_in[0];
    const int*   eiw = (const int*)d_in[1];
    const float* ea  = (const float*)d_in[2];
    const float *Wq0 = (const float*)d_in[3],  *bq0 = (const float*)d_in[4];
    const float *Wk0 = (const float*)d_in[5],  *bk0 = (const float*)d_in[6];
    const float *Wv0 = (const float*)d_in[7],  *bv0 = (const float*)d_in[8];
    const float *We0 = (const float*)d_in[9];
    const float *Ws0 = (const float*)d_in[10], *bs0 = (const float*)d_in[11];
    const float *Wq1 = (const float*)d_in[12], *bq1 = (const float*)d_in[13];
    const float *Wk1 = (const float*)d_in[14], *bk1 = (const float*)d_in[15];
    const float *Wv1 = (const float*)d_in[16], *bv1 = (const float*)d_in[17];
    const float *We1 = (const float*)d_in[18];
    const float *Ws1 = (const float*)d_in[19], *bs1 = (const float*)d_in[20];
    const float *Wc1 = (const float*)d_in[21], *bc1 = (const float*)d_in[22];
    const float *Wc2 = (const float*)d_in[23], *bc2 = (const float*)d_in[24];
    const float *Wc3 = (const float*)d_in[25], *bc3 = (const float*)d_in[26];

    const int n = in_sizes[0] / 2;
    const int E = in_sizes[2];

    float *Q, *Ha, *Hb, *cea;
    __half* KV;
    int *src, *dst, *deg, *rowptr, *fill, *csrc;
    cudaGetSymbolAddress((void**)&Q,      g_Q);
    cudaGetSymbolAddress((void**)&KV,     g_KV);
    cudaGetSymbolAddress((void**)&Ha,     g_Ha);
    cudaGetSymbolAddress((void**)&Hb,     g_Hb);
    cudaGetSymbolAddress((void**)&src,    g_src);
    cudaGetSymbolAddress((void**)&dst,    g_dst);
    cudaGetSymbolAddress((void**)&deg,    g_deg);
    cudaGetSymbolAddress((void**)&rowptr, g_rowptr);
    cudaGetSymbolAddress((void**)&fill,   g_fill);
    cudaGetSymbolAddress((void**)&csrc,   g_csrc);
    cudaGetSymbolAddress((void**)&cea,    g_cea);

    const int TB = 256;
    const int EB = (E + TB - 1) / TB;
    const int WB = (5 * 2048 + 1024 + TB - 1) / TB;
    dim3 nodeWarpGrid((n * 32 + TB - 1) / TB);
    dim3 nodeThreadGrid((n + TB - 1) / TB);
    dim3 tileGrid((n + 127) / 128);

    const int SMEM = 24576 * 4;   // 96 KB: A hi/lo (64 KB) + B plane (32 KB)
    cudaFuncSetAttribute(gemm4_hmma,      cudaFuncAttributeMaxDynamicSharedMemorySize, SMEM);
    cudaFuncSetAttribute(classifier_hmma, cudaFuncAttributeMaxDynamicSharedMemorySize, SMEM);

    cudaMemsetAsync(deg,  0, (n + 1) * sizeof(int));
    cudaMemsetAsync(fill, 0, n * sizeof(int));
    convert_ei_kernel<<<EB + WB, TB>>>(eiw, E, EB, src, dst, deg,                   // k1
                                       Wq1, Wk1, Wv1, Ws1, Wc1, Wc2);
    scan_kernel<<<1, 1024>>>(deg, rowptr, n);                                        // k2
    scatter_kernel<<<EB, TB>>>(src, dst, ea, rowptr, fill, csrc, cea, E);            // k3
    tconv0_kernel<<<nodeThreadGrid, TB>>>(rowptr, csrc, cea, x,                      // k4 <- profiled
                                          Wq0, bq0, Wk0, bk0, Wv0, bv0, Ws0, bs0,
                                          We0, Ha, n);
    gemm4_hmma<<<tileGrid, 256, SMEM>>>(Ha, bq1, Q, bk1, bv1, KV, bs1, Hb, n);       // k5
    tconv_kernel<<<nodeWarpGrid, TB>>>(rowptr, csrc, cea, Q, KV, We1, Hb, n);        // k6
    classifier_hmma<<<tileGrid, 256, SMEM>>>(Hb, bc1, bc2, Wc3, bc3,                 // k7
                                             (float*)d_out, n);
}